// round 1
// baseline (speedup 1.0000x reference)
#include <cuda_runtime.h>
#include <math.h>

// ---------------- problem constants ----------------
#define S_TOT  9616        // total sequence
#define RAZOR  8320        // (T-1)*H*W image tokens (rotated order: frames 1..8 first)
#define PF     1040        // tokens per frame
#define ROT    8576        // RAZOR + text_len : rotation pivot
#define NH     2
#define HD     128
#define PRE    2048        // main attention band half-width
#define WIN    301         // ratio mask window: |i-j| <= 301 is "in window"
#define BM     64
#define BN     64
#define NBLK   151         // ceil(9616/64)
#define SCALE  0.08838834764831845f   // 1/sqrt(128)

// rotated index -> original index
__device__ __forceinline__ int orig_idx(int r) { return r < ROT ? r + PF : r - ROT; }

// smem layout (floats)
#define QS_OFF 0
#define KS_OFF (BM*HD)                   // ks stride 132 (bank-conflict pad)
#define VS_OFF (KS_OFF + BN*132)
#define PS_OFF (VS_OFF + BN*HD)          // ps stride 65
#define SMEM_FLOATS (PS_OFF + BM*65)
#define SMEM_BYTES  (SMEM_FLOATS * 4)

// ---------------- main banded flash attention ----------------
__global__ __launch_bounds__(256)
void attn_kernel(const float* __restrict__ Q, const float* __restrict__ K,
                 const float* __restrict__ V, float* __restrict__ O)
{
    extern __shared__ float sm[];
    float* qs = sm + QS_OFF;   // [64][128]
    float* ks = sm + KS_OFF;   // [64][132]
    float* vs = sm + VS_OFF;   // [64][128]
    float* ps = sm + PS_OFF;   // [64][65]

    const int tile = blockIdx.x;
    const int head = blockIdx.y;
    const int r0   = tile * BM;
    const int tid  = threadIdx.x;
    const int tx   = tid & 15;
    const int ty   = tid >> 4;
    const int warp = tid >> 5;
    const int lane = tid & 31;

    // ---- load Q tile (rows r0..r0+63, rotated) ----
#pragma unroll
    for (int i = 0; i < 8; i++) {
        int row = warp * 8 + i;
        int r   = r0 + row;
        int gr  = orig_idx(min(r, S_TOT - 1));
        float4 v = *(const float4*)(Q + ((size_t)gr * NH + head) * HD + lane * 4);
        *(float4*)(qs + row * HD + lane * 4) = v;
    }
    __syncthreads();

    float  m_i[4], l_i[4];
    float4 acc_o[4][2];
#pragma unroll
    for (int i = 0; i < 4; i++) {
        m_i[i] = -INFINITY; l_i[i] = 0.f;
        acc_o[i][0] = make_float4(0.f, 0.f, 0.f, 0.f);
        acc_o[i][1] = make_float4(0.f, 0.f, 0.f, 0.f);
    }

    const bool in_razor = (r0 < RAZOR);   // tiles 0..129 (boundary 8320 = 130*64)
    int nseg, seg_lo[2], seg_hi[2];
    if (in_razor) {
        seg_lo[0] = max(0, tile - 32);  seg_hi[0] = min(130, tile + 33); // band blocks
        seg_lo[1] = 130;                seg_hi[1] = NBLK;                // tail blocks
        nseg = 2;
    } else {
        seg_lo[0] = 0; seg_hi[0] = NBLK; nseg = 1;
    }

    for (int seg = 0; seg < nseg; seg++)
    for (int blk = seg_lo[seg]; blk < seg_hi[seg]; blk++) {
        const int c0 = blk * BN;

        // ---- load K,V block ----
#pragma unroll
        for (int i = 0; i < 8; i++) {
            int row = warp * 8 + i;
            int c   = min(c0 + row, S_TOT - 1);
            int gc  = orig_idx(c);
            const float* kp = K + ((size_t)gc * NH + head) * HD + lane * 4;
            const float* vp = V + ((size_t)gc * NH + head) * HD + lane * 4;
            float4 kv = *(const float4*)kp;
            float4 vv = *(const float4*)vp;
            *(float4*)(ks + row * 132 + lane * 4) = kv;
            *(float4*)(vs + row * HD  + lane * 4) = vv;
        }
        __syncthreads();

        // ---- scores: 64x64 = (4x4 per thread), float4 over k-dim ----
        float acc[4][4];
#pragma unroll
        for (int i = 0; i < 4; i++)
#pragma unroll
            for (int j = 0; j < 4; j++) acc[i][j] = 0.f;

#pragma unroll 4
        for (int kk = 0; kk < HD; kk += 4) {
            float4 a[4], b[4];
#pragma unroll
            for (int i = 0; i < 4; i++) a[i] = *(float4*)(qs + (ty + 16 * i) * HD  + kk);
#pragma unroll
            for (int j = 0; j < 4; j++) b[j] = *(float4*)(ks + (tx + 16 * j) * 132 + kk);
#pragma unroll
            for (int i = 0; i < 4; i++)
#pragma unroll
                for (int j = 0; j < 4; j++)
                    acc[i][j] += a[i].x * b[j].x + a[i].y * b[j].y
                               + a[i].z * b[j].z + a[i].w * b[j].w;
        }

        // ---- mask + online softmax ----
#pragma unroll
        for (int i = 0; i < 4; i++) {
            int r = r0 + ty + 16 * i;
            float s[4];
            float bm = -INFINITY;
#pragma unroll
            for (int j = 0; j < 4; j++) {
                int c = c0 + tx + 16 * j;
                bool ok;
                if (in_razor) ok = (c >= RAZOR) ? (c < S_TOT) : (abs(r - c) <= PRE);
                else          ok = (c < S_TOT);
                s[j] = ok ? acc[i][j] * SCALE : -INFINITY;
                bm = fmaxf(bm, s[j]);
            }
#pragma unroll
            for (int off = 8; off >= 1; off >>= 1)
                bm = fmaxf(bm, __shfl_xor_sync(0xffffffffu, bm, off));
            float m_new = fmaxf(m_i[i], bm);       // finite: every block has >=1 valid col
            float sc = __expf(m_i[i] - m_new);     // 0 on first block
            l_i[i] *= sc;
            acc_o[i][0].x *= sc; acc_o[i][0].y *= sc; acc_o[i][0].z *= sc; acc_o[i][0].w *= sc;
            acc_o[i][1].x *= sc; acc_o[i][1].y *= sc; acc_o[i][1].z *= sc; acc_o[i][1].w *= sc;
            float psum = 0.f;
#pragma unroll
            for (int j = 0; j < 4; j++) {
                float p = __expf(s[j] - m_new);
                psum += p;
                ps[(ty + 16 * i) * 65 + tx + 16 * j] = p;
            }
            l_i[i] += psum;
            m_i[i]  = m_new;
        }
        __syncthreads();

        // ---- PV: acc_o += P(64x64) @ V(64x128) ----
#pragma unroll 4
        for (int c = 0; c < BN; c++) {
            float4 v0 = *(float4*)(vs + c * HD +      tx * 4);
            float4 v1 = *(float4*)(vs + c * HD + 64 + tx * 4);
#pragma unroll
            for (int i = 0; i < 4; i++) {
                float p = ps[(ty + 16 * i) * 65 + c];
                acc_o[i][0].x += p * v0.x; acc_o[i][0].y += p * v0.y;
                acc_o[i][0].z += p * v0.z; acc_o[i][0].w += p * v0.w;
                acc_o[i][1].x += p * v1.x; acc_o[i][1].y += p * v1.y;
                acc_o[i][1].z += p * v1.z; acc_o[i][1].w += p * v1.w;
            }
        }
        __syncthreads();
    }

    // ---- finalize: reduce l over 16 tx lanes, write rotated-back ----
#pragma unroll
    for (int i = 0; i < 4; i++) {
        float l = l_i[i];
#pragma unroll
        for (int off = 8; off >= 1; off >>= 1)
            l += __shfl_xor_sync(0xffffffffu, l, off);
        float inv = 1.0f / l;
        int r = r0 + ty + 16 * i;
        if (r < S_TOT) {
            int gr = orig_idx(r);   // rotate-back == write at original index
            float* op = O + ((size_t)gr * NH + head) * HD;
            float4 o0 = acc_o[i][0], o1 = acc_o[i][1];
            o0.x *= inv; o0.y *= inv; o0.z *= inv; o0.w *= inv;
            o1.x *= inv; o1.y *= inv; o1.z *= inv; o1.w *= inv;
            *(float4*)(op +      tx * 4) = o0;
            *(float4*)(op + 64 + tx * 4) = o1;
        }
    }
}

// ---------------- recall ratio kernels ----------------
// grid: (130, NH, 2)  z=0 -> local (stride 1), z=1 -> global (stride 8)
__global__ __launch_bounds__(256)
void ratio_kernel(const float* __restrict__ Q, const float* __restrict__ K,
                  float* __restrict__ ratio)
{
    const int warp = threadIdx.x >> 5;
    const int lane = threadIdx.x & 31;
    const int row  = blockIdx.x * 8 + warp;      // 0..1039
    const int head = blockIdx.y;
    const int type = blockIdx.z;
    const int stride = type ? 8 : 1;

    const int gq = PF + row * stride;            // rotated row -> original index
    float4 qv = *(const float4*)(Q + ((size_t)gq * NH + head) * HD + lane * 4);

    float m = -INFINITY, lt = 0.f, lw = 0.f;
    for (int j = 0; j < PF; j++) {
        int gk = PF + j * stride;
        float4 kv = *(const float4*)(K + ((size_t)gk * NH + head) * HD + lane * 4);
        float d = qv.x * kv.x + qv.y * kv.y + qv.z * kv.z + qv.w * kv.w;
#pragma unroll
        for (int off = 16; off >= 1; off >>= 1)
            d += __shfl_xor_sync(0xffffffffu, d, off);
        float s = d * SCALE;
        float m_new = fmaxf(m, s);
        float sc = __expf(m - m_new);
        float p  = __expf(s - m_new);
        lt = lt * sc + p;
        lw = lw * sc + ((abs(row - j) <= WIN) ? p : 0.f);
        m = m_new;
    }
    if (lane == 0)
        atomicAdd(&ratio[type * NH + head], (lw / lt) * (1.0f / (float)PF));
}

__global__ void zero_ratio(float* r) {
    if (threadIdx.x < 4) r[threadIdx.x] = 0.f;
}

// ---------------- launch ----------------
extern "C" void kernel_launch(void* const* d_in, const int* in_sizes, int n_in,
                              void* d_out, int out_size)
{
    const float* Q = (const float*)d_in[0];
    const float* K = (const float*)d_in[1];
    const float* V = (const float*)d_in[2];
    float* O     = (float*)d_out;
    float* ratio = O + (size_t)S_TOT * NH * HD;   // [ratio_local(2) | ratio_global(2)]

    cudaFuncSetAttribute(attn_kernel, cudaFuncAttributeMaxDynamicSharedMemorySize, SMEM_BYTES);

    zero_ratio<<<1, 32>>>(ratio);
    dim3 rg(130, NH, 2);
    ratio_kernel<<<rg, 256>>>(Q, K, ratio);
    dim3 ag(NBLK, NH);
    attn_kernel<<<ag, 256, SMEM_BYTES>>>(Q, K, V, O);
}

// round 2
// speedup vs baseline: 1.0012x; 1.0012x over previous
#include <cuda_runtime.h>
#include <math.h>

// ---------------- problem constants ----------------
#define S_TOT  9616        // total sequence
#define RAZOR  8320        // (T-1)*H*W image tokens (rotated order: frames 1..8 first)
#define PF     1040        // tokens per frame
#define ROT    8576        // RAZOR + text_len : rotation pivot
#define NH     2
#define HD     128
#define PRE    2048        // main attention band half-width
#define WIN    301         // ratio mask window: |i-j| <= 301 is "in window"
#define BM     64
#define BN     64
#define NBLK   151         // ceil(9616/64)
#define SCALE  0.08838834764831845f   // 1/sqrt(128)

// rotated index -> original index
__device__ __forceinline__ int orig_idx(int r) { return r < ROT ? r + PF : r - ROT; }

// smem layout (floats)
#define QS_OFF 0
#define KS_OFF (BM*HD)                   // ks stride 132 (bank-conflict pad)
#define VS_OFF (KS_OFF + BN*132)
#define PS_OFF (VS_OFF + BN*HD)          // ps stride 65
#define SMEM_FLOATS (PS_OFF + BM*65)
#define SMEM_BYTES  (SMEM_FLOATS * 4)

// ---------------- main banded flash attention ----------------
__global__ __launch_bounds__(256)
void attn_kernel(const float* __restrict__ Q, const float* __restrict__ K,
                 const float* __restrict__ V, float* __restrict__ O)
{
    extern __shared__ float sm[];
    float* qs = sm + QS_OFF;   // [64][128]
    float* ks = sm + KS_OFF;   // [64][132]
    float* vs = sm + VS_OFF;   // [64][128]
    float* ps = sm + PS_OFF;   // [64][65]

    const int tile = blockIdx.x;
    const int head = blockIdx.y;
    const int r0   = tile * BM;
    const int tid  = threadIdx.x;
    const int tx   = tid & 15;
    const int ty   = tid >> 4;
    const int warp = tid >> 5;
    const int lane = tid & 31;

    // ---- load Q tile (rows r0..r0+63, rotated) ----
#pragma unroll
    for (int i = 0; i < 8; i++) {
        int row = warp * 8 + i;
        int r   = r0 + row;
        int gr  = orig_idx(min(r, S_TOT - 1));
        float4 v = *(const float4*)(Q + ((size_t)gr * NH + head) * HD + lane * 4);
        *(float4*)(qs + row * HD + lane * 4) = v;
    }
    __syncthreads();

    float  m_i[4], l_i[4];
    float4 acc_o[4][2];
#pragma unroll
    for (int i = 0; i < 4; i++) {
        m_i[i] = -INFINITY; l_i[i] = 0.f;
        acc_o[i][0] = make_float4(0.f, 0.f, 0.f, 0.f);
        acc_o[i][1] = make_float4(0.f, 0.f, 0.f, 0.f);
    }

    const bool in_razor = (r0 < RAZOR);   // tiles 0..129 (boundary 8320 = 130*64)
    int nseg, seg_lo[2], seg_hi[2];
    if (in_razor) {
        seg_lo[0] = max(0, tile - 32);  seg_hi[0] = min(130, tile + 33); // band blocks
        seg_lo[1] = 130;                seg_hi[1] = NBLK;                // tail blocks
        nseg = 2;
    } else {
        seg_lo[0] = 0; seg_hi[0] = NBLK; nseg = 1;
    }

    for (int seg = 0; seg < nseg; seg++)
    for (int blk = seg_lo[seg]; blk < seg_hi[seg]; blk++) {
        const int c0 = blk * BN;

        // ---- load K,V block ----
#pragma unroll
        for (int i = 0; i < 8; i++) {
            int row = warp * 8 + i;
            int c   = min(c0 + row, S_TOT - 1);
            int gc  = orig_idx(c);
            const float* kp = K + ((size_t)gc * NH + head) * HD + lane * 4;
            const float* vp = V + ((size_t)gc * NH + head) * HD + lane * 4;
            float4 kv = *(const float4*)kp;
            float4 vv = *(const float4*)vp;
            *(float4*)(ks + row * 132 + lane * 4) = kv;
            *(float4*)(vs + row * HD  + lane * 4) = vv;
        }
        __syncthreads();

        // ---- scores: 64x64 = (4x4 per thread), float4 over k-dim ----
        float acc[4][4];
#pragma unroll
        for (int i = 0; i < 4; i++)
#pragma unroll
            for (int j = 0; j < 4; j++) acc[i][j] = 0.f;

#pragma unroll 4
        for (int kk = 0; kk < HD; kk += 4) {
            float4 a[4], b[4];
#pragma unroll
            for (int i = 0; i < 4; i++) a[i] = *(float4*)(qs + (ty + 16 * i) * HD  + kk);
#pragma unroll
            for (int j = 0; j < 4; j++) b[j] = *(float4*)(ks + (tx + 16 * j) * 132 + kk);
#pragma unroll
            for (int i = 0; i < 4; i++)
#pragma unroll
                for (int j = 0; j < 4; j++)
                    acc[i][j] += a[i].x * b[j].x + a[i].y * b[j].y
                               + a[i].z * b[j].z + a[i].w * b[j].w;
        }

        // ---- mask + online softmax ----
#pragma unroll
        for (int i = 0; i < 4; i++) {
            int r = r0 + ty + 16 * i;
            float s[4];
            float bm = -INFINITY;
#pragma unroll
            for (int j = 0; j < 4; j++) {
                int c = c0 + tx + 16 * j;
                bool ok;
                if (in_razor) ok = (c >= RAZOR) ? (c < S_TOT) : (abs(r - c) <= PRE);
                else          ok = (c < S_TOT);
                s[j] = ok ? acc[i][j] * SCALE : -INFINITY;
                bm = fmaxf(bm, s[j]);
            }
#pragma unroll
            for (int off = 8; off >= 1; off >>= 1)
                bm = fmaxf(bm, __shfl_xor_sync(0xffffffffu, bm, off));
            float m_new = fmaxf(m_i[i], bm);       // finite: every block has >=1 valid col
            float sc = __expf(m_i[i] - m_new);     // 0 on first block
            l_i[i] *= sc;
            acc_o[i][0].x *= sc; acc_o[i][0].y *= sc; acc_o[i][0].z *= sc; acc_o[i][0].w *= sc;
            acc_o[i][1].x *= sc; acc_o[i][1].y *= sc; acc_o[i][1].z *= sc; acc_o[i][1].w *= sc;
            float psum = 0.f;
#pragma unroll
            for (int j = 0; j < 4; j++) {
                float p = __expf(s[j] - m_new);
                psum += p;
                ps[(ty + 16 * i) * 65 + tx + 16 * j] = p;
            }
            l_i[i] += psum;
            m_i[i]  = m_new;
        }
        __syncthreads();

        // ---- PV: acc_o += P(64x64) @ V(64x128) ----
#pragma unroll 4
        for (int c = 0; c < BN; c++) {
            float4 v0 = *(float4*)(vs + c * HD +      tx * 4);
            float4 v1 = *(float4*)(vs + c * HD + 64 + tx * 4);
#pragma unroll
            for (int i = 0; i < 4; i++) {
                float p = ps[(ty + 16 * i) * 65 + c];
                acc_o[i][0].x += p * v0.x; acc_o[i][0].y += p * v0.y;
                acc_o[i][0].z += p * v0.z; acc_o[i][0].w += p * v0.w;
                acc_o[i][1].x += p * v1.x; acc_o[i][1].y += p * v1.y;
                acc_o[i][1].z += p * v1.z; acc_o[i][1].w += p * v1.w;
            }
        }
        __syncthreads();
    }

    // ---- finalize: reduce l over 16 tx lanes, write rotated-back ----
#pragma unroll
    for (int i = 0; i < 4; i++) {
        float l = l_i[i];
#pragma unroll
        for (int off = 8; off >= 1; off >>= 1)
            l += __shfl_xor_sync(0xffffffffu, l, off);
        float inv = 1.0f / l;
        int r = r0 + ty + 16 * i;
        if (r < S_TOT) {
            int gr = orig_idx(r);   // rotate-back == write at original index
            float* op = O + ((size_t)gr * NH + head) * HD;
            float4 o0 = acc_o[i][0], o1 = acc_o[i][1];
            o0.x *= inv; o0.y *= inv; o0.z *= inv; o0.w *= inv;
            o1.x *= inv; o1.y *= inv; o1.z *= inv; o1.w *= inv;
            *(float4*)(op +      tx * 4) = o0;
            *(float4*)(op + 64 + tx * 4) = o1;
        }
    }
}

// ---------------- recall ratio kernels ----------------
// grid: (130, NH, 2)  z=0 -> local (stride 1), z=1 -> global (stride 8)
__global__ __launch_bounds__(256)
void ratio_kernel(const float* __restrict__ Q, const float* __restrict__ K,
                  float* __restrict__ ratio)
{
    const int warp = threadIdx.x >> 5;
    const int lane = threadIdx.x & 31;
    const int row  = blockIdx.x * 8 + warp;      // 0..1039
    const int head = blockIdx.y;
    const int type = blockIdx.z;
    const int stride = type ? 8 : 1;

    const int gq = PF + row * stride;            // rotated row -> original index
    float4 qv = *(const float4*)(Q + ((size_t)gq * NH + head) * HD + lane * 4);

    float m = -INFINITY, lt = 0.f, lw = 0.f;
    for (int j = 0; j < PF; j++) {
        int gk = PF + j * stride;
        float4 kv = *(const float4*)(K + ((size_t)gk * NH + head) * HD + lane * 4);
        float d = qv.x * kv.x + qv.y * kv.y + qv.z * kv.z + qv.w * kv.w;
#pragma unroll
        for (int off = 16; off >= 1; off >>= 1)
            d += __shfl_xor_sync(0xffffffffu, d, off);
        float s = d * SCALE;
        float m_new = fmaxf(m, s);
        float sc = __expf(m - m_new);
        float p  = __expf(s - m_new);
        lt = lt * sc + p;
        lw = lw * sc + ((abs(row - j) <= WIN) ? p : 0.f);
        m = m_new;
    }
    if (lane == 0)
        atomicAdd(&ratio[type * NH + head], (lw / lt) * (1.0f / (float)PF));
}

__global__ void zero_ratio(float* r) {
    if (threadIdx.x < 4) r[threadIdx.x] = 0.f;
}

// ---------------- launch ----------------
extern "C" void kernel_launch(void* const* d_in, const int* in_sizes, int n_in,
                              void* d_out, int out_size)
{
    const float* Q = (const float*)d_in[0];
    const float* K = (const float*)d_in[1];
    const float* V = (const float*)d_in[2];
    float* O     = (float*)d_out;
    float* ratio = O + (size_t)S_TOT * NH * HD;   // [ratio_local(2) | ratio_global(2)]

    cudaFuncSetAttribute(attn_kernel, cudaFuncAttributeMaxDynamicSharedMemorySize, SMEM_BYTES);

    zero_ratio<<<1, 32>>>(ratio);
    dim3 rg(130, NH, 2);
    ratio_kernel<<<rg, 256>>>(Q, K, ratio);
    dim3 ag(NBLK, NH);
    attn_kernel<<<ag, 256, SMEM_BYTES>>>(Q, K, V, O);
}